// round 2
// baseline (speedup 1.0000x reference)
#include <cuda_runtime.h>
#include <cstdint>
#include <cmath>

static __device__ float g_scratch[24u * 1024u * 1024u];

#define OFF_EMB     ((size_t)0)
#define OFF_DEMB    (OFF_EMB    + 2048*512)
#define OFF_XP0F    (OFF_DEMB   + 2048*512)
#define OFF_XP0B    (OFF_XP0F   + 2048*2048)
#define OFF_XP      (OFF_XP0B   + 2048*2048)
#define OFF_OF      (OFF_XP     + 2048*2048)
#define OFF_OB      (OFF_OF     + 2048*512)
#define OFF_CAT     (OFF_OB     + 2048*512)
#define OFF_L1      (OFF_CAT    + 2048*1024)
#define OFF_L2      (OFF_L1     + 2048*512)
#define OFF_TOPCTX  (OFF_L2     + 2048*512)
#define OFF_H0      (OFF_TOPCTX + 2048*1024)
#define OFF_H1      (OFF_H0   + 16384)
#define OFF_CC      (OFF_H1   + 16384)
#define OFF_HSAV    (OFF_CC   + 16384)
#define OFF_CSAV    (OFF_HSAV + 16384)
#define OFF_DHA     (OFF_CSAV + 16384)
#define OFF_DHB     (OFF_DHA  + 4*16384)
#define OFF_DC      (OFF_DHB  + 4*16384)
#define OFF_CTX     (OFF_DC   + 4*16384)
#define OFF_LI      (OFF_CTX  + 16384)
#define OFF_Q       (OFF_LI   + 32*1024)
#define OFF_END     (OFF_Q    + 16384)
static_assert(OFF_END <= (size_t)24u * 1024u * 1024u, "scratch overflow");

__device__ __forceinline__ float warp_sum(float v) {
#pragma unroll
    for (int o = 16; o > 0; o >>= 1) v += __shfl_xor_sync(0xffffffffu, v, o);
    return v;
}
__device__ __forceinline__ float sigf(float x) { return 1.f / (1.f + expf(-x)); }

__global__ void embed_kernel(const int* __restrict__ tok, const float* __restrict__ tab,
                             float* __restrict__ out, int total) {
    int idx = blockIdx.x * 256 + threadIdx.x;
    if (idx >= total) return;
    int row = idx >> 9, col = idx & 511;
    int t = tok[row];
    out[idx] = (t == 0) ? 0.f : tab[(size_t)t * 512 + col];
}

// C[M,N] = A[M,K] @ W[N,K]^T (+bias). 128x128 tile, BK=8, 256 thr, 8x8 micro.
__global__ __launch_bounds__(256) void sgemm_nt(
    const float* __restrict__ A, const float* __restrict__ W,
    const float* __restrict__ bias, float* __restrict__ C,
    int M, int N, int K)
{
    __shared__ float As[8][128];
    __shared__ float Ws[8][128];
    int bm = blockIdx.y * 128, bn = blockIdx.x * 128;
    int tid = threadIdx.x;
    int tx = tid & 15, ty = tid >> 4;
    int lr = tid >> 1, lc = (tid & 1) * 4;
    const float* Ap = A + (size_t)(bm + lr) * K + lc;
    const float* Wp = W + (size_t)(bn + lr) * K + lc;
    float acc[8][8];
#pragma unroll
    for (int i = 0; i < 8; i++)
#pragma unroll
        for (int j = 0; j < 8; j++) acc[i][j] = 0.f;

    for (int k0 = 0; k0 < K; k0 += 8) {
        float4 av = *(const float4*)(Ap + k0);
        float4 wv = *(const float4*)(Wp + k0);
        __syncthreads();
        As[lc + 0][lr] = av.x; As[lc + 1][lr] = av.y;
        As[lc + 2][lr] = av.z; As[lc + 3][lr] = av.w;
        Ws[lc + 0][lr] = wv.x; Ws[lc + 1][lr] = wv.y;
        Ws[lc + 2][lr] = wv.z; Ws[lc + 3][lr] = wv.w;
        __syncthreads();
#pragma unroll
        for (int kk = 0; kk < 8; kk++) {
            float a[8], b[8];
            *(float4*)(a)     = *(const float4*)(&As[kk][ty * 8]);
            *(float4*)(a + 4) = *(const float4*)(&As[kk][ty * 8 + 4]);
            *(float4*)(b)     = *(const float4*)(&Ws[kk][tx * 8]);
            *(float4*)(b + 4) = *(const float4*)(&Ws[kk][tx * 8 + 4]);
#pragma unroll
            for (int i = 0; i < 8; i++)
#pragma unroll
                for (int j = 0; j < 8; j++) acc[i][j] = fmaf(a[i], b[j], acc[i][j]);
        }
    }
    float bv[8];
#pragma unroll
    for (int j = 0; j < 8; j++) bv[j] = bias ? bias[bn + tx * 8 + j] : 0.f;
#pragma unroll
    for (int i = 0; i < 8; i++) {
        float* cp = C + (size_t)(bm + ty * 8 + i) * N + bn + tx * 8;
#pragma unroll
        for (int j = 0; j < 8; j++) cp[j] = acc[i][j] + bv[j];
    }
}

// one masked LSTM step (x-proj precomputed). grid(32,64), warp = unit j.
__global__ __launch_bounds__(256) void lstm_step_kernel(
    const float* __restrict__ xproj, const float* __restrict__ Whh,
    const float* __restrict__ bias,
    const float* __restrict__ h_in, float* __restrict__ h_out,
    float* __restrict__ c, float* __restrict__ out,
    const int* __restrict__ lens, int t)
{
    int b = blockIdx.x;
    __shared__ float hs[512];
    int tid = threadIdx.x;
    for (int k = tid; k < 512; k += 256) hs[k] = h_in[b * 512 + k];
    __syncthreads();
    int wid = tid >> 5, lane = tid & 31;
    int j = blockIdx.y * 8 + wid;
    const float* wh = Whh + (size_t)j * 512 + lane;
    float a0 = 0, a1 = 0, a2 = 0, a3 = 0;
#pragma unroll
    for (int kk = 0; kk < 512; kk += 32) {
        float hv = hs[kk + lane];
        a0 = fmaf(wh[kk],          hv, a0);
        a1 = fmaf(wh[262144 + kk], hv, a1);
        a2 = fmaf(wh[524288 + kk], hv, a2);
        a3 = fmaf(wh[786432 + kk], hv, a3);
    }
    a0 = warp_sum(a0); a1 = warp_sum(a1); a2 = warp_sum(a2); a3 = warp_sum(a3);
    if (lane == 0) {
        const float* xp = xproj + (size_t)(b * 64 + t) * 2048;
        float gi = a0 + xp[j]        + bias[j];
        float gf = a1 + xp[512 + j]  + bias[512 + j];
        float gg = a2 + xp[1024 + j] + bias[1024 + j];
        float go = a3 + xp[1536 + j] + bias[1536 + j];
        bool v = t < lens[b];
        float c2 = sigf(gf) * c[b * 512 + j] + sigf(gi) * tanhf(gg);
        float h2 = sigf(go) * tanhf(c2);
        h_out[b * 512 + j] = v ? h2 : hs[j];
        if (v) c[b * 512 + j] = c2;
        out[(size_t)(b * 64 + t) * 512 + j] = v ? h2 : 0.f;
    }
}

// full decoder LSTM cell: x GEMV + h GEMV fused. grid(32,64).
__global__ __launch_bounds__(256) void lstm_cell_kernel(
    const float* __restrict__ x, int Kx,
    const float* __restrict__ Wih, const float* __restrict__ Whh,
    const float* __restrict__ bias,
    const float* __restrict__ h_in, float* __restrict__ h_out,
    float* __restrict__ c, int resid)
{
    int b = blockIdx.x;
    __shared__ float xs[1024];
    __shared__ float hs[512];
    int tid = threadIdx.x;
    for (int k = tid; k < Kx; k += 256) xs[k] = x[b * Kx + k];
    for (int k = tid; k < 512; k += 256) hs[k] = h_in[b * 512 + k];
    __syncthreads();
    int wid = tid >> 5, lane = tid & 31;
    int j = blockIdx.y * 8 + wid;
    const float* wi = Wih + (size_t)j * Kx + lane;
    size_t rs = (size_t)512 * Kx;
    float a0 = 0, a1 = 0, a2 = 0, a3 = 0;
    for (int kk = 0; kk < Kx; kk += 32) {
        float xv = xs[kk + lane];
        a0 = fmaf(wi[kk],          xv, a0);
        a1 = fmaf(wi[rs + kk],     xv, a1);
        a2 = fmaf(wi[2 * rs + kk], xv, a2);
        a3 = fmaf(wi[3 * rs + kk], xv, a3);
    }
    const float* wh = Whh + (size_t)j * 512 + lane;
#pragma unroll
    for (int kk = 0; kk < 512; kk += 32) {
        float hv = hs[kk + lane];
        a0 = fmaf(wh[kk],          hv, a0);
        a1 = fmaf(wh[262144 + kk], hv, a1);
        a2 = fmaf(wh[524288 + kk], hv, a2);
        a3 = fmaf(wh[786432 + kk], hv, a3);
    }
    a0 = warp_sum(a0); a1 = warp_sum(a1); a2 = warp_sum(a2); a3 = warp_sum(a3);
    if (lane == 0) {
        float gi = a0 + bias[j];
        float gf = a1 + bias[512 + j];
        float gg = a2 + bias[1024 + j];
        float go = a3 + bias[1536 + j];
        float c2 = sigf(gf) * c[b * 512 + j] + sigf(gi) * tanhf(gg);
        float h2 = sigf(go) * tanhf(c2);
        c[b * 512 + j] = c2;
        h_out[b * 512 + j] = h2 + (resid ? xs[j] : 0.f);
    }
}

__global__ __launch_bounds__(256) void qproj_kernel(
    const float* __restrict__ top, const float* __restrict__ attn_w,
    float* __restrict__ q)
{
    int b = blockIdx.x;
    __shared__ float ts[512];
    int tid = threadIdx.x;
    for (int k = tid; k < 512; k += 256) ts[k] = top[b * 512 + k];
    __syncthreads();
    int wid = tid >> 5, lane = tid & 31;
    int j0 = blockIdx.y * 64 + wid * 8;
#pragma unroll
    for (int u = 0; u < 8; u++) {
        const float* w = attn_w + (size_t)(j0 + u) * 512;
        float a = 0.f;
#pragma unroll
        for (int kk = 0; kk < 512; kk += 32) a = fmaf(w[kk + lane], ts[kk + lane], a);
        a = warp_sum(a);
        if (lane == 0) q[b * 512 + j0 + u] = a;
    }
}

// scores, masked softmax, ctx, topctx pack, attn weights to d_out.
__global__ __launch_bounds__(256) void attn2_kernel(
    const float* __restrict__ top, const float* __restrict__ enc_out,
    const float* __restrict__ q, const int* __restrict__ lens,
    float* __restrict__ ctx, float* __restrict__ topctx,
    float* __restrict__ attn_out, int t)
{
    int b = blockIdx.x;
    __shared__ float qs[512];
    __shared__ float sc[64];
    int tid = threadIdx.x;
    for (int k = tid; k < 512; k += 256) qs[k] = q[b * 512 + k];
    __syncthreads();
    int wid = tid >> 5, lane = tid & 31;
    int len = lens[b];
#pragma unroll
    for (int si = 0; si < 8; si++) {
        int s = wid * 8 + si;
        const float* er = enc_out + (size_t)(b * 64 + s) * 512;
        float a = 0.f;
#pragma unroll
        for (int kk = 0; kk < 512; kk += 32) a = fmaf(er[kk + lane], qs[kk + lane], a);
        a = warp_sum(a);
        if (lane == 0) sc[s] = (s < len) ? a : -INFINITY;
    }
    __syncthreads();
    if (wid == 0) {
        float v1 = sc[lane], v2 = sc[lane + 32];
        float m = fmaxf(v1, v2);
#pragma unroll
        for (int o = 16; o > 0; o >>= 1) m = fmaxf(m, __shfl_xor_sync(0xffffffffu, m, o));
        float e1 = expf(v1 - m), e2 = expf(v2 - m);
        float inv = 1.f / warp_sum(e1 + e2);
        e1 *= inv; e2 *= inv;
        sc[lane] = e1; sc[lane + 32] = e2;
        size_t ao = (size_t)b * 4096 + (size_t)t * 64;
        attn_out[ao + lane] = e1;
        attn_out[ao + lane + 32] = e2;
    }
    __syncthreads();
    size_t row = (size_t)(b * 64 + t) * 1024;
    for (int j = tid; j < 512; j += 256) {
        float a = 0.f;
#pragma unroll 8
        for (int s = 0; s < 64; s++)
            a = fmaf(sc[s], enc_out[(size_t)(b * 64 + s) * 512 + j], a);
        ctx[b * 512 + j] = a;
        topctx[row + 512 + j] = a;
        topctx[row + j] = top[b * 512 + j];
    }
}

__global__ void concat2_kernel(float* __restrict__ dst, const float* __restrict__ a,
                               const float* __restrict__ b, int total) {
    int idx = blockIdx.x * 256 + threadIdx.x;
    if (idx >= total) return;
    int r = idx >> 10, cidx = idx & 1023;
    dst[idx] = (cidx < 512) ? a[r * 512 + cidx] : b[r * 512 + cidx - 512];
}
__global__ void concat_li_kernel(float* __restrict__ li, const float* __restrict__ demb,
                                 const float* __restrict__ ctx, int t) {
    int idx = blockIdx.x * 256 + threadIdx.x;
    if (idx >= 32768) return;
    int bb = idx >> 10, cidx = idx & 1023;
    li[idx] = (cidx < 512) ? demb[(size_t)(bb * 64 + t) * 512 + cidx]
                           : ctx[bb * 512 + cidx - 512];
}
__global__ void add2_kernel(float* __restrict__ d, const float* __restrict__ a,
                            const float* __restrict__ b, int n) {
    int i = blockIdx.x * 256 + threadIdx.x;
    if (i < n) d[i] = a[i] + b[i];
}
__global__ void addip_kernel(float* __restrict__ d, const float* __restrict__ a, int n) {
    int i = blockIdx.x * 256 + threadIdx.x;
    if (i < n) d[i] += a[i];
}

extern "C" void kernel_launch(void* const* d_in, const int* in_sizes, int n_in,
                              void* d_out, int out_size) {
    const int*   src_tokens  = (const int*)d_in[0];
    const int*   src_lengths = (const int*)d_in[1];
    const int*   tgt_tokens  = (const int*)d_in[2];
    const float* enc_embed   = (const float*)d_in[3];
    const float* enc_l0_wih  = (const float*)d_in[4];
    const float* enc_l0_whh  = (const float*)d_in[5];
    const float* enc_l0_b    = (const float*)d_in[6];
    const float* proj_w      = (const float*)d_in[7];
    const float* proj_b      = (const float*)d_in[8];
    const float* enc_wih     = (const float*)d_in[9];
    const float* enc_whh     = (const float*)d_in[10];
    const float* enc_b       = (const float*)d_in[11];
    const float* dec_embed   = (const float*)d_in[12];
    const float* dec0_wih    = (const float*)d_in[13];
    const float* dec0_whh    = (const float*)d_in[14];
    const float* dec0_b      = (const float*)d_in[15];
    const float* dec_wih     = (const float*)d_in[16];
    const float* dec_whh     = (const float*)d_in[17];
    const float* dec_b       = (const float*)d_in[18];
    const float* attn_w      = (const float*)d_in[19];
    const float* out_w       = (const float*)d_in[20];
    const float* out_b       = (const float*)d_in[21];

    float* base = nullptr;
    cudaGetSymbolAddress((void**)&base, g_scratch);

    float* emb    = base + OFF_EMB;
    float* demb   = base + OFF_DEMB;
    float* xp0f   = base + OFF_XP0F;
    float* xp0b   = base + OFF_XP0B;
    float* xp     = base + OFF_XP;
    float* ofbuf  = base + OFF_OF;
    float* obbuf  = base + OFF_OB;
    float* cat    = base + OFF_CAT;
    float* l1     = base + OFF_L1;
    float* l2     = base + OFF_L2;
    float* topctx = base + OFF_TOPCTX;
    float* h0     = base + OFF_H0;
    float* h1     = base + OFF_H1;
    float* cc     = base + OFF_CC;
    float* hsav   = base + OFF_HSAV;
    float* csav   = base + OFF_CSAV;
    float* dhA    = base + OFF_DHA;
    float* dhB    = base + OFF_DHB;
    float* dc     = base + OFF_DC;
    float* ctx    = base + OFF_CTX;
    float* li     = base + OFF_LI;
    float* qbuf   = base + OFF_Q;

    float* logits   = (float*)d_out;
    float* attn_out = (float*)d_out + ((size_t)2048 * 32000);

    embed_kernel<<<4096, 256>>>(src_tokens, enc_embed, emb, 2048 * 512);
    embed_kernel<<<4096, 256>>>(tgt_tokens, dec_embed, demb, 2048 * 512);

    sgemm_nt<<<dim3(16, 16), 256>>>(emb, enc_l0_wih, nullptr, xp0f, 2048, 2048, 512);
    sgemm_nt<<<dim3(16, 16), 256>>>(emb, enc_l0_wih + (size_t)2048 * 512, nullptr, xp0b,
                                    2048, 2048, 512);

    // encoder layer 0 forward
    cudaMemsetAsync(h0, 0, 16384 * 4);
    cudaMemsetAsync(cc, 0, 16384 * 4);
    for (int t = 0; t < 64; t++) {
        float* hi = (t & 1) ? h1 : h0;
        float* ho = (t & 1) ? h0 : h1;
        lstm_step_kernel<<<dim3(32, 64), 256>>>(xp0f, enc_l0_whh, enc_l0_b,
                                                hi, ho, cc, ofbuf, src_lengths, t);
    }
    cudaMemcpyAsync(hsav, h0, 16384 * 4, cudaMemcpyDeviceToDevice);
    cudaMemcpyAsync(csav, cc, 16384 * 4, cudaMemcpyDeviceToDevice);

    // encoder layer 0 backward
    cudaMemsetAsync(h0, 0, 16384 * 4);
    cudaMemsetAsync(cc, 0, 16384 * 4);
    for (int k = 0; k < 64; k++) {
        int t = 63 - k;
        float* hi = (k & 1) ? h1 : h0;
        float* ho = (k & 1) ? h0 : h1;
        lstm_step_kernel<<<dim3(32, 64), 256>>>(xp0b, enc_l0_whh + (size_t)2048 * 512,
                                                enc_l0_b + 2048, hi, ho, cc, obbuf,
                                                src_lengths, t);
    }
    add2_kernel<<<64, 256>>>(dhA, hsav, h0, 16384);
    add2_kernel<<<64, 256>>>(dc, csav, cc, 16384);

    concat2_kernel<<<8192, 256>>>(cat, ofbuf, obbuf, 2048 * 1024);
    sgemm_nt<<<dim3(4, 16), 256>>>(cat, proj_w, proj_b, l1, 2048, 512, 1024);

    // encoder layers 1..3
    float* cur = l1;
    float* nxt = l2;
    for (int i = 0; i < 3; i++) {
        sgemm_nt<<<dim3(16, 16), 256>>>(cur, enc_wih + (size_t)i * 2048 * 512, nullptr,
                                        xp, 2048, 2048, 512);
        cudaMemsetAsync(h0, 0, 16384 * 4);
        cudaMemsetAsync(cc, 0, 16384 * 4);
        for (int t = 0; t < 64; t++) {
            float* hi = (t & 1) ? h1 : h0;
            float* ho = (t & 1) ? h0 : h1;
            lstm_step_kernel<<<dim3(32, 64), 256>>>(xp, enc_whh + (size_t)i * 2048 * 512,
                                                    enc_b + i * 2048, hi, ho, cc, nxt,
                                                    src_lengths, t);
        }
        if (i >= 1) addip_kernel<<<4096, 256>>>(nxt, cur, 2048 * 512);
        cudaMemcpyAsync(dhA + (size_t)(i + 1) * 16384, h0, 16384 * 4,
                        cudaMemcpyDeviceToDevice);
        cudaMemcpyAsync(dc + (size_t)(i + 1) * 16384, cc, 16384 * 4,
                        cudaMemcpyDeviceToDevice);
        float* tmp = cur; cur = nxt; nxt = tmp;
    }
    float* enc_out = cur;

    // decoder
    cudaMemsetAsync(ctx, 0, 16384 * 4);
    float* hA = dhA;
    float* hB = dhB;
    for (int t = 0; t < 64; t++) {
        concat_li_kernel<<<128, 256>>>(li, demb, ctx, t);
        lstm_cell_kernel<<<dim3(32, 64), 256>>>(li, 1024, dec0_wih, dec0_whh, dec0_b,
                                                hA, hB, dc, 0);
        lstm_cell_kernel<<<dim3(32, 64), 256>>>(hB, 512, dec_wih, dec_whh, dec_b,
                                                hA + 16384, hB + 16384, dc + 16384, 0);
        lstm_cell_kernel<<<dim3(32, 64), 256>>>(hB + 16384, 512,
                                                dec_wih + (size_t)2048 * 512,
                                                dec_whh + (size_t)2048 * 512,
                                                dec_b + 2048,
                                                hA + 2 * 16384, hB + 2 * 16384,
                                                dc + 2 * 16384, 1);
        lstm_cell_kernel<<<dim3(32, 64), 256>>>(hB + 2 * 16384, 512,
                                                dec_wih + (size_t)2 * 2048 * 512,
                                                dec_whh + (size_t)2 * 2048 * 512,
                                                dec_b + 2 * 2048,
                                                hA + 3 * 16384, hB + 3 * 16384,
                                                dc + 3 * 16384, 1);
        qproj_kernel<<<dim3(32, 8), 256>>>(hB + 3 * 16384, attn_w, qbuf);
        attn2_kernel<<<32, 256>>>(hB + 3 * 16384, enc_out, qbuf, src_lengths,
                                  ctx, topctx, attn_out, t);
        float* tmp = hA; hA = hB; hB = tmp;
    }

    // deferred logits GEMM: [2048,1024] @ [32000,1024]^T
    sgemm_nt<<<dim3(250, 16), 256>>>(topctx, out_w, out_b, logits, 2048, 32000, 1024);
}